// round 1
// baseline (speedup 1.0000x reference)
#include <cuda_runtime.h>

#define CB 2
#define CL 2048
#define CE 2048
#define CH 16
#define CHD 128
#define CM (CB*CL)      // 4096
#define C3E (3*CE)      // 6144

// ---------------- scratch (device globals; no allocations allowed) ----------
static __device__ float g_qkv[(size_t)CM * C3E];        // [B*L, 3E]
static __device__ float g_q[(size_t)CB*CH*CL*CHD];      // [b,h,l,d]
static __device__ float g_k[(size_t)CB*CH*CL*CHD];
static __device__ float g_v[(size_t)CB*CH*CL*CHD];
static __device__ float g_y[(size_t)CM * CE];           // [b,l,e]

// ---------------- GEMM: C[M,N] = A[M,K] * B[N,K]^T (fp32) -------------------
// 128x128 tile, BK=16, 256 threads, 8x8 per thread in 2x2 blocks of 4x4.
__global__ __launch_bounds__(256, 2)
void sgemm_nt(const float* __restrict__ A, const float* __restrict__ B,
              float* __restrict__ C, int M, int N, int K) {
    __shared__ float As[16][132];
    __shared__ float Bs[16][132];
    const int bm = blockIdx.y * 128;
    const int bn = blockIdx.x * 128;
    const int tid = threadIdx.x;
    const int cy = tid >> 4;    // 0..15
    const int cx = tid & 15;    // 0..15

    float acc[2][2][4][4];
#pragma unroll
    for (int a = 0; a < 2; a++)
#pragma unroll
        for (int b = 0; b < 2; b++)
#pragma unroll
            for (int i = 0; i < 4; i++)
#pragma unroll
                for (int j = 0; j < 4; j++) acc[a][b][i][j] = 0.f;

    for (int k0 = 0; k0 < K; k0 += 16) {
#pragma unroll
        for (int t = 0; t < 2; t++) {
            int f = t * 256 + tid;     // 0..511
            int row = f >> 2;          // 0..127
            int kq = f & 3;            // float4 index within BK
            float4 va = *(const float4*)(A + (size_t)(bm + row) * K + k0 + kq * 4);
            As[kq*4+0][row] = va.x;
            As[kq*4+1][row] = va.y;
            As[kq*4+2][row] = va.z;
            As[kq*4+3][row] = va.w;
            float4 vb = *(const float4*)(B + (size_t)(bn + row) * K + k0 + kq * 4);
            Bs[kq*4+0][row] = vb.x;
            Bs[kq*4+1][row] = vb.y;
            Bs[kq*4+2][row] = vb.z;
            Bs[kq*4+3][row] = vb.w;
        }
        __syncthreads();
#pragma unroll
        for (int kk = 0; kk < 16; kk++) {
            float4 a0 = *(const float4*)&As[kk][cy * 4];
            float4 a1 = *(const float4*)&As[kk][64 + cy * 4];
            float4 b0 = *(const float4*)&Bs[kk][cx * 4];
            float4 b1 = *(const float4*)&Bs[kk][64 + cx * 4];
            float av[2][4] = {{a0.x, a0.y, a0.z, a0.w}, {a1.x, a1.y, a1.z, a1.w}};
            float bv[2][4] = {{b0.x, b0.y, b0.z, b0.w}, {b1.x, b1.y, b1.z, b1.w}};
#pragma unroll
            for (int ib = 0; ib < 2; ib++)
#pragma unroll
                for (int jb = 0; jb < 2; jb++)
#pragma unroll
                    for (int i = 0; i < 4; i++)
#pragma unroll
                        for (int j = 0; j < 4; j++)
                            acc[ib][jb][i][j] += av[ib][i] * bv[jb][j];
        }
        __syncthreads();
    }

#pragma unroll
    for (int ib = 0; ib < 2; ib++)
#pragma unroll
        for (int i = 0; i < 4; i++)
#pragma unroll
            for (int jb = 0; jb < 2; jb++) {
                float4 o = make_float4(acc[ib][jb][i][0], acc[ib][jb][i][1],
                                       acc[ib][jb][i][2], acc[ib][jb][i][3]);
                *(float4*)(C + (size_t)(bm + ib * 64 + cy * 4 + i) * N
                           + bn + jb * 64 + cx * 4) = o;
            }
}

// ---------------- RoPE + qkv split into head-major layout -------------------
// one thread per (b, l, h, pair p<64); handles q/k rope pair + v pair copy.
__global__ __launch_bounds__(256)
void rope_split(const float* __restrict__ rope) {
    int idx = blockIdx.x * 256 + threadIdx.x;   // < B*L*H*64 = 4194304
    int p = idx & 63;
    int h = (idx >> 6) & 15;
    int l = (idx >> 10) & (CL - 1);
    int b = idx >> 21;

    const float* qkv = g_qkv + (size_t)(b * CL + l) * C3E;
    float s = rope[l * CHD + p * 2 + 0];
    float c = rope[l * CHD + p * 2 + 1];
    int e = h * CHD + 2 * p;
    float q0 = qkv[e],          q1 = qkv[e + 1];
    float k0 = qkv[CE + e],     k1 = qkv[CE + e + 1];
    float v0 = qkv[2*CE + e],   v1 = qkv[2*CE + e + 1];

    size_t off = ((size_t)(b * CH + h) * CL + l) * CHD + 2 * p;
    g_q[off]     = q0 * c - q1 * s;
    g_q[off + 1] = q1 * c + q0 * s;
    g_k[off]     = k0 * c - k1 * s;
    g_k[off + 1] = k1 * c + k0 * s;
    g_v[off]     = v0;
    g_v[off + 1] = v1;
}

// ---------------- causal flash attention (fp32) -----------------------------
#define BQ 64
#define BKT 32
#define QSTR 132
#define SSTR 36
#define FLASH_SMEM ((BQ*QSTR + 2*BKT*QSTR + BQ*SSTR + 3*BQ) * 4)  // 77568 B

__global__ __launch_bounds__(256, 2)
void flash_attn() {
    extern __shared__ float sm[];
    float* Qs  = sm;                    // [64][132]
    float* Ks  = Qs + BQ * QSTR;        // [32][132]
    float* Vs  = Ks + BKT * QSTR;       // [32][132]
    float* Ss  = Vs + BKT * QSTR;       // [64][36]
    float* smm = Ss + BQ * SSTR;        // m[64]
    float* sml = smm + BQ;              // l[64]
    float* sma = sml + BQ;              // alpha[64]

    const int qt  = gridDim.x - 1 - blockIdx.x;   // long CTAs first
    const int bh  = blockIdx.y;
    const int tid = threadIdx.x;
    const int cy  = tid >> 4;   // 0..15
    const int cx  = tid & 15;   // 0..15
    const float scale = 0.08838834764831845f;     // 1/sqrt(128)

    const float* qp = g_q + (size_t)bh * CL * CHD + (size_t)qt * BQ * CHD;
#pragma unroll
    for (int t = 0; t < 8; t++) {
        int f = t * 256 + tid;          // 2048 float4
        int row = f >> 5, dq = f & 31;
        *(float4*)(Qs + row * QSTR + dq * 4) =
            *(const float4*)(qp + row * CHD + dq * 4);
    }
    if (tid < BQ) { smm[tid] = -1e30f; sml[tid] = 0.f; }

    float o[4][8];
#pragma unroll
    for (int i = 0; i < 4; i++)
#pragma unroll
        for (int j = 0; j < 8; j++) o[i][j] = 0.f;

    const int nk = 2 * qt + 2;
    const float* kbase = g_k + (size_t)bh * CL * CHD;
    const float* vbase = g_v + (size_t)bh * CL * CHD;

    for (int kt = 0; kt < nk; kt++) {
        __syncthreads();
        const float* kp = kbase + (size_t)kt * BKT * CHD;
        const float* vp = vbase + (size_t)kt * BKT * CHD;
#pragma unroll
        for (int t = 0; t < 4; t++) {
            int f = t * 256 + tid;      // 1024 float4 each
            int row = f >> 5, dq = f & 31;
            *(float4*)(Ks + row * QSTR + dq * 4) =
                *(const float4*)(kp + row * CHD + dq * 4);
            *(float4*)(Vs + row * QSTR + dq * 4) =
                *(const float4*)(vp + row * CHD + dq * 4);
        }
        __syncthreads();

        // S = Q K^T : thread owns rows cy*4+i, cols cx*2+j
        float s[4][2] = {};
#pragma unroll 4
        for (int d = 0; d < CHD; d += 4) {
            float4 a[4], bb[2];
#pragma unroll
            for (int i = 0; i < 4; i++)
                a[i] = *(const float4*)(Qs + (cy * 4 + i) * QSTR + d);
#pragma unroll
            for (int j = 0; j < 2; j++)
                bb[j] = *(const float4*)(Ks + (cx * 2 + j) * QSTR + d);
#pragma unroll
            for (int i = 0; i < 4; i++)
#pragma unroll
                for (int j = 0; j < 2; j++)
                    s[i][j] += a[i].x * bb[j].x + a[i].y * bb[j].y
                             + a[i].z * bb[j].z + a[i].w * bb[j].w;
        }
#pragma unroll
        for (int i = 0; i < 4; i++) {
            int row = cy * 4 + i;
            int qg = qt * BQ + row;
#pragma unroll
            for (int j = 0; j < 2; j++) {
                int kg = kt * BKT + cx * 2 + j;
                float vv = s[i][j] * scale;
                if (kg > qg) vv = -1e30f;
                Ss[row * SSTR + cx * 2 + j] = vv;
            }
        }
        __syncthreads();

        // online softmax: 4 threads per row
        {
            int row = tid >> 2, sub = tid & 3;
            float vals[8];
            float mx = -1e30f;
#pragma unroll
            for (int c = 0; c < 8; c++) {
                vals[c] = Ss[row * SSTR + sub * 8 + c];
                mx = fmaxf(mx, vals[c]);
            }
            mx = fmaxf(mx, __shfl_xor_sync(0xffffffffu, mx, 1));
            mx = fmaxf(mx, __shfl_xor_sync(0xffffffffu, mx, 2));
            float mo = smm[row];
            float mn = fmaxf(mo, mx);
            float ssum = 0.f;
#pragma unroll
            for (int c = 0; c < 8; c++) {
                float pz = __expf(vals[c] - mn);
                Ss[row * SSTR + sub * 8 + c] = pz;
                ssum += pz;
            }
            ssum += __shfl_xor_sync(0xffffffffu, ssum, 1);
            ssum += __shfl_xor_sync(0xffffffffu, ssum, 2);
            if (sub == 0) {
                float al = __expf(mo - mn);
                sma[row] = al;
                sml[row] = sml[row] * al + ssum;
                smm[row] = mn;
            }
        }
        __syncthreads();

        // rescale O, then O += P @ V : thread owns rows cy*4+i, cols cx*8..cx*8+7
        float al[4];
#pragma unroll
        for (int i = 0; i < 4; i++) al[i] = sma[cy * 4 + i];
#pragma unroll
        for (int i = 0; i < 4; i++)
#pragma unroll
            for (int j = 0; j < 8; j++) o[i][j] *= al[i];

#pragma unroll 8
        for (int k = 0; k < BKT; k++) {
            float p[4];
#pragma unroll
            for (int i = 0; i < 4; i++) p[i] = Ss[(cy * 4 + i) * SSTR + k];
            float4 v0 = *(const float4*)(Vs + k * QSTR + cx * 8);
            float4 v1 = *(const float4*)(Vs + k * QSTR + cx * 8 + 4);
#pragma unroll
            for (int i = 0; i < 4; i++) {
                o[i][0] += p[i] * v0.x;  o[i][1] += p[i] * v0.y;
                o[i][2] += p[i] * v0.z;  o[i][3] += p[i] * v0.w;
                o[i][4] += p[i] * v1.x;  o[i][5] += p[i] * v1.y;
                o[i][6] += p[i] * v1.z;  o[i][7] += p[i] * v1.w;
            }
        }
    }

    // epilogue: y[b, q, h*128 + d]
    const int b = bh >> 4, h = bh & 15;
#pragma unroll
    for (int i = 0; i < 4; i++) {
        int row = cy * 4 + i;
        int qg = qt * BQ + row;
        float inv = 1.f / sml[row];
        float* dst = g_y + (size_t)(b * CL + qg) * CE + h * CHD + cx * 8;
        *(float4*)dst =
            make_float4(o[i][0]*inv, o[i][1]*inv, o[i][2]*inv, o[i][3]*inv);
        *(float4*)(dst + 4) =
            make_float4(o[i][4]*inv, o[i][5]*inv, o[i][6]*inv, o[i][7]*inv);
    }
}

// ---------------- host launcher ---------------------------------------------
extern "C" void kernel_launch(void* const* d_in, const int* in_sizes, int n_in,
                              void* d_out, int out_size) {
    const float* x      = (const float*)d_in[0];
    const float* rope   = (const float*)d_in[1];
    const float* w_attn = (const float*)d_in[2];
    const float* w_proj = (const float*)d_in[3];
    float* out = (float*)d_out;

    float *qkv_p, *y_p;
    cudaGetSymbolAddress((void**)&qkv_p, g_qkv);
    cudaGetSymbolAddress((void**)&y_p,   g_y);

    // 1) qkv = x @ w_attn^T   [4096, 6144]
    sgemm_nt<<<dim3(C3E / 128, CM / 128), 256>>>(x, w_attn, qkv_p, CM, C3E, CE);

    // 2) rope + split into head-major q/k/v
    rope_split<<<(CB * CL * CH * 64) / 256, 256>>>(rope);

    // 3) causal flash attention -> g_y [b,l,e]
    cudaFuncSetAttribute(flash_attn, cudaFuncAttributeMaxDynamicSharedMemorySize,
                         FLASH_SMEM);
    flash_attn<<<dim3(CL / BQ, CB * CH), 256, FLASH_SMEM>>>();

    // 4) out = y @ w_proj^T   [4096, 2048]
    sgemm_nt<<<dim3(CE / 128, CM / 128), 256>>>(y_p, w_proj, out, CM, CE, CE);
}

// round 4
// speedup vs baseline: 2.0241x; 2.0241x over previous
#include <cuda_runtime.h>
#include <cuda_fp16.h>
#include <cstdint>

#define CB 2
#define CL 2048
#define CE 2048
#define CH 16
#define CHD 128
#define CM (CB*CL)      // 4096
#define C3E (3*CE)      // 6144

// ---------------- scratch (device globals; no allocations allowed) ----------
static __device__ float  g_qkv[(size_t)CM * C3E];        // [B*L, 3E] fp32
static __device__ float  g_q[(size_t)CB*CH*CL*CHD];      // [b,h,l,d]
static __device__ float  g_k[(size_t)CB*CH*CL*CHD];
static __device__ float  g_v[(size_t)CB*CH*CL*CHD];
static __device__ __half g_xh[(size_t)CM * CE];          // x in fp16
static __device__ __half g_wah[(size_t)C3E * CE];        // w_attn fp16
static __device__ __half g_wph[(size_t)CE * CE];         // w_proj fp16
static __device__ __half g_yh[(size_t)CM * CE];          // attention out fp16

// ---------------- PTX helpers -------------------------------------------------
__device__ __forceinline__ uint32_t smem_u32(const void* p) {
    uint32_t a;
    asm("{ .reg .u64 t; cvta.to.shared.u64 t, %1; cvt.u32.u64 %0, t; }"
        : "=r"(a) : "l"(p));
    return a;
}
__device__ __forceinline__ void cp16(uint32_t dst, const void* src) {
    asm volatile("cp.async.cg.shared.global [%0], [%1], 16;"
                 :: "r"(dst), "l"(src));
}
#define CP_COMMIT() asm volatile("cp.async.commit_group;" ::: "memory")
#define CP_WAIT0()  asm volatile("cp.async.wait_group 0;" ::: "memory")

__device__ __forceinline__ void ldsm_x4(uint32_t& r0, uint32_t& r1,
                                        uint32_t& r2, uint32_t& r3, uint32_t a) {
    asm volatile("ldmatrix.sync.aligned.m8n8.x4.shared.b16 {%0,%1,%2,%3}, [%4];"
                 : "=r"(r0), "=r"(r1), "=r"(r2), "=r"(r3) : "r"(a));
}
__device__ __forceinline__ void ldsm_x2(uint32_t& r0, uint32_t& r1, uint32_t a) {
    asm volatile("ldmatrix.sync.aligned.m8n8.x2.shared.b16 {%0,%1}, [%2];"
                 : "=r"(r0), "=r"(r1) : "r"(a));
}
__device__ __forceinline__ void mma16816(float* c, const uint32_t* a,
                                         const uint32_t* b) {
    asm volatile("mma.sync.aligned.m16n8k16.row.col.f32.f16.f16.f32 "
                 "{%0,%1,%2,%3}, {%4,%5,%6,%7}, {%8,%9}, {%0,%1,%2,%3};"
                 : "+f"(c[0]), "+f"(c[1]), "+f"(c[2]), "+f"(c[3])
                 : "r"(a[0]), "r"(a[1]), "r"(a[2]), "r"(a[3]),
                   "r"(b[0]), "r"(b[1]));
}

// ---------------- HMMA fp16 GEMM: C[M,N] = A[M,K] * B[N,K]^T (fp32 out) -----
// 128x128 CTA tile, BK=32, 8 warps (2x4), warp tile 64x32, cp.async dbl-buf.
#define BM 128
#define BN 128
#define BK 32
#define ASTR 40   // halves per smem row (32 + 8 pad); 80B, 16B-aligned stride

__global__ __launch_bounds__(256, 2)
void hgemm_mma(const __half* __restrict__ A, const __half* __restrict__ B,
               float* __restrict__ C, int M, int N, int K) {
    __shared__ __align__(16) __half As[2][BM * ASTR];
    __shared__ __align__(16) __half Bs[2][BN * ASTR];

    const int tid  = threadIdx.x;
    const int lane = tid & 31;
    const int wid  = tid >> 5;
    const int wm   = (wid >> 2) * 64;   // warp m offset (0 / 64)
    const int wn   = (wid & 3) * 32;    // warp n offset (0/32/64/96)
    const int bm   = blockIdx.y * BM;
    const int bn   = blockIdx.x * BN;

    const __half* Ab = A + (size_t)bm * K;
    const __half* Bb = B + (size_t)bn * K;

    float acc[4][4][4];
#pragma unroll
    for (int mt = 0; mt < 4; mt++)
#pragma unroll
        for (int nt = 0; nt < 4; nt++)
#pragma unroll
            for (int i = 0; i < 4; i++) acc[mt][nt][i] = 0.f;

    // per-thread load coords: 512 16B-chunks per tile, 2 per thread
    const int r0c = tid >> 1;            // rows 0..127 (chunk group 0)
    const int c0c = (tid & 1) * 2;       // chunk 0/2  -> cols 0,16
    // each thread does chunks (r0c, c0c) and (r0c, c0c+1)

    const uint32_t smA = smem_u32(As);
    const uint32_t smB = smem_u32(Bs);

    auto load_stage = [&](int s, int kc) {
        const __half* ap = Ab + kc * BK;
        const __half* bp = Bb + kc * BK;
        uint32_t da = smA + (uint32_t)(s * BM * ASTR * 2);
        uint32_t db = smB + (uint32_t)(s * BN * ASTR * 2);
#pragma unroll
        for (int cc = 0; cc < 2; cc++) {
            int col8 = (c0c + cc) * 8;
            cp16(da + (r0c * ASTR + col8) * 2, ap + (size_t)r0c * K + col8);
            cp16(db + (r0c * ASTR + col8) * 2, bp + (size_t)r0c * K + col8);
        }
    };

    const int nk = K / BK;
    load_stage(0, 0);
    CP_COMMIT();

    for (int kc = 0; kc < nk; kc++) {
        const int s = kc & 1;
        CP_WAIT0();
        __syncthreads();
        if (kc + 1 < nk) {
            load_stage(s ^ 1, kc + 1);
            CP_COMMIT();
        }

        const uint32_t baseA = smA + (uint32_t)(s * BM * ASTR * 2);
        const uint32_t baseB = smB + (uint32_t)(s * BN * ASTR * 2);
#pragma unroll
        for (int ks = 0; ks < 2; ks++) {
            uint32_t a[4][4], b[4][2];
#pragma unroll
            for (int mt = 0; mt < 4; mt++) {
                uint32_t addr = baseA +
                    ((wm + mt * 16 + (lane & 15)) * ASTR +
                     ks * 16 + (lane >> 4) * 8) * 2;
                ldsm_x4(a[mt][0], a[mt][1], a[mt][2], a[mt][3], addr);
            }
#pragma unroll
            for (int nt = 0; nt < 4; nt++) {
                uint32_t addr = baseB +
                    ((wn + nt * 8 + (lane & 7)) * ASTR +
                     ks * 16 + ((lane >> 3) & 1) * 8) * 2;
                ldsm_x2(b[nt][0], b[nt][1], addr);
            }
#pragma unroll
            for (int mt = 0; mt < 4; mt++)
#pragma unroll
                for (int nt = 0; nt < 4; nt++)
                    mma16816(acc[mt][nt], a[mt], b[nt]);
        }
        __syncthreads();
    }

    // epilogue: fp32 writes
    const int tr = lane >> 2;           // 0..7
    const int tc = (lane & 3) * 2;      // 0,2,4,6
#pragma unroll
    for (int mt = 0; mt < 4; mt++) {
#pragma unroll
        for (int nt = 0; nt < 4; nt++) {
            int r = bm + wm + mt * 16 + tr;
            int c = bn + wn + nt * 8 + tc;
            *(float2*)(C + (size_t)r * N + c) =
                make_float2(acc[mt][nt][0], acc[mt][nt][1]);
            *(float2*)(C + (size_t)(r + 8) * N + c) =
                make_float2(acc[mt][nt][2], acc[mt][nt][3]);
        }
    }
}

// ---------------- fp32 -> fp16 convert ---------------------------------------
__global__ __launch_bounds__(256)
void f32to16(const float* __restrict__ s, __half* __restrict__ d) {
    int i = blockIdx.x * 256 + threadIdx.x;
    float4 v = *(const float4*)(s + (size_t)i * 4);
    __half2 h0 = __floats2half2_rn(v.x, v.y);
    __half2 h1 = __floats2half2_rn(v.z, v.w);
    uint2 o;
    o.x = *(const uint32_t*)&h0;
    o.y = *(const uint32_t*)&h1;
    *(uint2*)(d + (size_t)i * 4) = o;
}

// ---------------- RoPE + qkv split into head-major layout -------------------
__global__ __launch_bounds__(256)
void rope_split(const float* __restrict__ rope) {
    int idx = blockIdx.x * 256 + threadIdx.x;   // < B*L*H*64
    int p = idx & 63;
    int h = (idx >> 6) & 15;
    int l = (idx >> 10) & (CL - 1);
    int b = idx >> 21;

    const float* qkv = g_qkv + (size_t)(b * CL + l) * C3E;
    float s = rope[l * CHD + p * 2 + 0];
    float c = rope[l * CHD + p * 2 + 1];
    int e = h * CHD + 2 * p;
    float q0 = qkv[e],          q1 = qkv[e + 1];
    float k0 = qkv[CE + e],     k1 = qkv[CE + e + 1];
    float v0 = qkv[2*CE + e],   v1 = qkv[2*CE + e + 1];

    size_t off = ((size_t)(b * CH + h) * CL + l) * CHD + 2 * p;
    g_q[off]     = q0 * c - q1 * s;
    g_q[off + 1] = q1 * c + q0 * s;
    g_k[off]     = k0 * c - k1 * s;
    g_k[off + 1] = k1 * c + k0 * s;
    g_v[off]     = v0;
    g_v[off + 1] = v1;
}

// ---------------- causal flash attention (fp32) -----------------------------
#define BQ 64
#define BKT 32
#define QSTR 132
#define SSTR 36
#define FLASH_SMEM ((BQ*QSTR + 2*BKT*QSTR + BQ*SSTR + 3*BQ) * 4)  // 77568 B

__global__ __launch_bounds__(256, 2)
void flash_attn() {
    extern __shared__ float smf[];
    float* Qs  = smf;
    float* Ks  = Qs + BQ * QSTR;
    float* Vs  = Ks + BKT * QSTR;
    float* Ss  = Vs + BKT * QSTR;
    float* smm = Ss + BQ * SSTR;
    float* sml = smm + BQ;
    float* sma = sml + BQ;

    const int qt  = gridDim.x - 1 - blockIdx.x;
    const int bh  = blockIdx.y;
    const int tid = threadIdx.x;
    const int cy  = tid >> 4;
    const int cx  = tid & 15;
    const float scale = 0.08838834764831845f;

    const float* qp = g_q + (size_t)bh * CL * CHD + (size_t)qt * BQ * CHD;
#pragma unroll
    for (int t = 0; t < 8; t++) {
        int f = t * 256 + tid;
        int row = f >> 5, dq = f & 31;
        *(float4*)(Qs + row * QSTR + dq * 4) =
            *(const float4*)(qp + row * CHD + dq * 4);
    }
    if (tid < BQ) { smm[tid] = -1e30f; sml[tid] = 0.f; }

    float o[4][8];
#pragma unroll
    for (int i = 0; i < 4; i++)
#pragma unroll
        for (int j = 0; j < 8; j++) o[i][j] = 0.f;

    const int nk = 2 * qt + 2;
    const float* kbase = g_k + (size_t)bh * CL * CHD;
    const float* vbase = g_v + (size_t)bh * CL * CHD;

    for (int kt = 0; kt < nk; kt++) {
        __syncthreads();
        const float* kp = kbase + (size_t)kt * BKT * CHD;
        const float* vp = vbase + (size_t)kt * BKT * CHD;
#pragma unroll
        for (int t = 0; t < 4; t++) {
            int f = t * 256 + tid;
            int row = f >> 5, dq = f & 31;
            *(float4*)(Ks + row * QSTR + dq * 4) =
                *(const float4*)(kp + row * CHD + dq * 4);
            *(float4*)(Vs + row * QSTR + dq * 4) =
                *(const float4*)(vp + row * CHD + dq * 4);
        }
        __syncthreads();

        float s[4][2] = {};
#pragma unroll 4
        for (int d = 0; d < CHD; d += 4) {
            float4 a[4], bb[2];
#pragma unroll
            for (int i = 0; i < 4; i++)
                a[i] = *(const float4*)(Qs + (cy * 4 + i) * QSTR + d);
#pragma unroll
            for (int j = 0; j < 2; j++)
                bb[j] = *(const float4*)(Ks + (cx * 2 + j) * QSTR + d);
#pragma unroll
            for (int i = 0; i < 4; i++)
#pragma unroll
                for (int j = 0; j < 2; j++)
                    s[i][j] += a[i].x * bb[j].x + a[i].y * bb[j].y
                             + a[i].z * bb[j].z + a[i].w * bb[j].w;
        }
#pragma unroll
        for (int i = 0; i < 4; i++) {
            int row = cy * 4 + i;
            int qg = qt * BQ + row;
#pragma unroll
            for (int j = 0; j < 2; j++) {
                int kg = kt * BKT + cx * 2 + j;
                float vv = s[i][j] * scale;
                if (kg > qg) vv = -1e30f;
                Ss[row * SSTR + cx * 2 + j] = vv;
            }
        }
        __syncthreads();

        {
            int row = tid >> 2, sub = tid & 3;
            float vals[8];
            float mx = -1e30f;
#pragma unroll
            for (int c = 0; c < 8; c++) {
                vals[c] = Ss[row * SSTR + sub * 8 + c];
                mx = fmaxf(mx, vals[c]);
            }
            mx = fmaxf(mx, __shfl_xor_sync(0xffffffffu, mx, 1));
            mx = fmaxf(mx, __shfl_xor_sync(0xffffffffu, mx, 2));
            float mo = smm[row];
            float mn = fmaxf(mo, mx);
            float ssum = 0.f;
#pragma unroll
            for (int c = 0; c < 8; c++) {
                float pz = __expf(vals[c] - mn);
                Ss[row * SSTR + sub * 8 + c] = pz;
                ssum += pz;
            }
            ssum += __shfl_xor_sync(0xffffffffu, ssum, 1);
            ssum += __shfl_xor_sync(0xffffffffu, ssum, 2);
            if (sub == 0) {
                float al = __expf(mo - mn);
                sma[row] = al;
                sml[row] = sml[row] * al + ssum;
                smm[row] = mn;
            }
        }
        __syncthreads();

        float al[4];
#pragma unroll
        for (int i = 0; i < 4; i++) al[i] = sma[cy * 4 + i];
#pragma unroll
        for (int i = 0; i < 4; i++)
#pragma unroll
            for (int j = 0; j < 8; j++) o[i][j] *= al[i];

#pragma unroll 8
        for (int k = 0; k < BKT; k++) {
            float p[4];
#pragma unroll
            for (int i = 0; i < 4; i++) p[i] = Ss[(cy * 4 + i) * SSTR + k];
            float4 v0 = *(const float4*)(Vs + k * QSTR + cx * 8);
            float4 v1 = *(const float4*)(Vs + k * QSTR + cx * 8 + 4);
#pragma unroll
            for (int i = 0; i < 4; i++) {
                o[i][0] += p[i] * v0.x;  o[i][1] += p[i] * v0.y;
                o[i][2] += p[i] * v0.z;  o[i][3] += p[i] * v0.w;
                o[i][4] += p[i] * v1.x;  o[i][5] += p[i] * v1.y;
                o[i][6] += p[i] * v1.z;  o[i][7] += p[i] * v1.w;
            }
        }
    }

    // epilogue: write fp16 directly into g_yh[b, q, h*128 + d]
    const int b = bh >> 4, h = bh & 15;
#pragma unroll
    for (int i = 0; i < 4; i++) {
        int row = cy * 4 + i;
        int qg = qt * BQ + row;
        float inv = 1.f / sml[row];
        __half2 h0 = __floats2half2_rn(o[i][0] * inv, o[i][1] * inv);
        __half2 h1 = __floats2half2_rn(o[i][2] * inv, o[i][3] * inv);
        __half2 h2 = __floats2half2_rn(o[i][4] * inv, o[i][5] * inv);
        __half2 h3 = __floats2half2_rn(o[i][6] * inv, o[i][7] * inv);
        uint4 pk;
        pk.x = *(const uint32_t*)&h0; pk.y = *(const uint32_t*)&h1;
        pk.z = *(const uint32_t*)&h2; pk.w = *(const uint32_t*)&h3;
        *(uint4*)(g_yh + (size_t)(b * CL + qg) * CE + h * CHD + cx * 8) = pk;
    }
}

// ---------------- host launcher ---------------------------------------------
extern "C" void kernel_launch(void* const* d_in, const int* in_sizes, int n_in,
                              void* d_out, int out_size) {
    const float* x      = (const float*)d_in[0];
    const float* rope   = (const float*)d_in[1];
    const float* w_attn = (const float*)d_in[2];
    const float* w_proj = (const float*)d_in[3];
    float* out = (float*)d_out;

    float *qkv_p;
    __half *xh_p, *wah_p, *wph_p, *yh_p;
    cudaGetSymbolAddress((void**)&qkv_p, g_qkv);
    cudaGetSymbolAddress((void**)&xh_p,  g_xh);
    cudaGetSymbolAddress((void**)&wah_p, g_wah);
    cudaGetSymbolAddress((void**)&wph_p, g_wph);
    cudaGetSymbolAddress((void**)&yh_p,  g_yh);

    static bool attr_set = false;
    if (!attr_set) {
        cudaFuncSetAttribute(flash_attn, cudaFuncAttributeMaxDynamicSharedMemorySize,
                             FLASH_SMEM);
        attr_set = true;
    }

    // 0) fp32 -> fp16 converts
    f32to16<<<(CM * CE / 4) / 256, 256>>>(x, xh_p);
    f32to16<<<(C3E * CE / 4) / 256, 256>>>(w_attn, wah_p);
    f32to16<<<(CE * CE / 4) / 256, 256>>>(w_proj, wph_p);

    // 1) qkv = x @ w_attn^T   [4096, 6144]  (HMMA fp16)
    hgemm_mma<<<dim3(C3E / BN, CM / BM), 256>>>(xh_p, wah_p, qkv_p, CM, C3E, CE);

    // 2) rope + split into head-major q/k/v
    rope_split<<<(CB * CL * CH * 64) / 256, 256>>>(rope);

    // 3) causal flash attention -> g_yh (fp16)
    flash_attn<<<dim3(CL / BQ, CB * CH), 256, FLASH_SMEM>>>();

    // 4) out = y @ w_proj^T   [4096, 2048]  (HMMA fp16)
    hgemm_mma<<<dim3(CE / BN, CM / BM), 256>>>(yh_p, wph_p, out, CM, CE, CE);
}

// round 6
// speedup vs baseline: 5.7973x; 2.8642x over previous
#include <cuda_runtime.h>
#include <cuda_fp16.h>
#include <cstdint>

#define CB 2
#define CL 2048
#define CE 2048
#define CH 16
#define CHD 128
#define CM (CB*CL)      // 4096
#define C3E (3*CE)      // 6144

// ---------------- scratch (device globals; no allocations allowed) ----------
static __device__ float  g_qkv[(size_t)CM * C3E];        // [B*L, 3E] fp32
static __device__ __half g_qh[(size_t)CB*CH*CL*CHD];     // [b,h,l,d] fp16
static __device__ __half g_kh[(size_t)CB*CH*CL*CHD];
static __device__ __half g_vh[(size_t)CB*CH*CL*CHD];
static __device__ __half g_xh[(size_t)CM * CE];          // x in fp16
static __device__ __half g_wah[(size_t)C3E * CE];        // w_attn fp16
static __device__ __half g_wph[(size_t)CE * CE];         // w_proj fp16
static __device__ __half g_yh[(size_t)CM * CE];          // attention out fp16

// ---------------- PTX helpers -------------------------------------------------
__device__ __forceinline__ uint32_t smem_u32(const void* p) {
    uint32_t a;
    asm("{ .reg .u64 t; cvta.to.shared.u64 t, %1; cvt.u32.u64 %0, t; }"
        : "=r"(a) : "l"(p));
    return a;
}
__device__ __forceinline__ void cp16(uint32_t dst, const void* src) {
    asm volatile("cp.async.cg.shared.global [%0], [%1], 16;"
                 :: "r"(dst), "l"(src));
}
#define CP_COMMIT() asm volatile("cp.async.commit_group;" ::: "memory")
#define CP_WAIT0()  asm volatile("cp.async.wait_group 0;" ::: "memory")

__device__ __forceinline__ void ldsm_x4(uint32_t& r0, uint32_t& r1,
                                        uint32_t& r2, uint32_t& r3, uint32_t a) {
    asm volatile("ldmatrix.sync.aligned.m8n8.x4.shared.b16 {%0,%1,%2,%3}, [%4];"
                 : "=r"(r0), "=r"(r1), "=r"(r2), "=r"(r3) : "r"(a));
}
__device__ __forceinline__ void ldsm_x4t(uint32_t& r0, uint32_t& r1,
                                         uint32_t& r2, uint32_t& r3, uint32_t a) {
    asm volatile("ldmatrix.sync.aligned.m8n8.x4.trans.shared.b16 {%0,%1,%2,%3}, [%4];"
                 : "=r"(r0), "=r"(r1), "=r"(r2), "=r"(r3) : "r"(a));
}
__device__ __forceinline__ void ldsm_x2(uint32_t& r0, uint32_t& r1, uint32_t a) {
    asm volatile("ldmatrix.sync.aligned.m8n8.x2.shared.b16 {%0,%1}, [%2];"
                 : "=r"(r0), "=r"(r1) : "r"(a));
}
__device__ __forceinline__ void mma16816(float* c, const uint32_t* a,
                                         const uint32_t* b) {
    asm volatile("mma.sync.aligned.m16n8k16.row.col.f32.f16.f16.f32 "
                 "{%0,%1,%2,%3}, {%4,%5,%6,%7}, {%8,%9}, {%0,%1,%2,%3};"
                 : "+f"(c[0]), "+f"(c[1]), "+f"(c[2]), "+f"(c[3])
                 : "r"(a[0]), "r"(a[1]), "r"(a[2]), "r"(a[3]),
                   "r"(b[0]), "r"(b[1]));
}
__device__ __forceinline__ float ex2f(float x) {
    float y;
    asm("ex2.approx.ftz.f32 %0, %1;" : "=f"(y) : "f"(x));
    return y;
}

// ---------------- HMMA fp16 GEMM: C[M,N] = A[M,K] * B[N,K]^T (fp32 out) -----
#define BM 128
#define BN 128
#define BK 32
#define ASTR 40

__global__ __launch_bounds__(256, 2)
void hgemm_mma(const __half* __restrict__ A, const __half* __restrict__ B,
               float* __restrict__ C, int M, int N, int K) {
    __shared__ __align__(16) __half As[2][BM * ASTR];
    __shared__ __align__(16) __half Bs[2][BN * ASTR];

    const int tid  = threadIdx.x;
    const int lane = tid & 31;
    const int wid  = tid >> 5;
    const int wm   = (wid >> 2) * 64;
    const int wn   = (wid & 3) * 32;
    const int bm   = blockIdx.y * BM;
    const int bn   = blockIdx.x * BN;

    const __half* Ab = A + (size_t)bm * K;
    const __half* Bb = B + (size_t)bn * K;

    float acc[4][4][4];
#pragma unroll
    for (int mt = 0; mt < 4; mt++)
#pragma unroll
        for (int nt = 0; nt < 4; nt++)
#pragma unroll
            for (int i = 0; i < 4; i++) acc[mt][nt][i] = 0.f;

    const int r0c = tid >> 1;
    const int c0c = (tid & 1) * 2;
    const uint32_t smA = smem_u32(As);
    const uint32_t smB = smem_u32(Bs);

    auto load_stage = [&](int s, int kc) {
        const __half* ap = Ab + kc * BK;
        const __half* bp = Bb + kc * BK;
        uint32_t da = smA + (uint32_t)(s * BM * ASTR * 2);
        uint32_t db = smB + (uint32_t)(s * BN * ASTR * 2);
#pragma unroll
        for (int cc = 0; cc < 2; cc++) {
            int col8 = (c0c + cc) * 8;
            cp16(da + (r0c * ASTR + col8) * 2, ap + (size_t)r0c * K + col8);
            cp16(db + (r0c * ASTR + col8) * 2, bp + (size_t)r0c * K + col8);
        }
    };

    const int nk = K / BK;
    load_stage(0, 0);
    CP_COMMIT();

    for (int kc = 0; kc < nk; kc++) {
        const int s = kc & 1;
        CP_WAIT0();
        __syncthreads();
        if (kc + 1 < nk) {
            load_stage(s ^ 1, kc + 1);
            CP_COMMIT();
        }

        const uint32_t baseA = smA + (uint32_t)(s * BM * ASTR * 2);
        const uint32_t baseB = smB + (uint32_t)(s * BN * ASTR * 2);
#pragma unroll
        for (int ks = 0; ks < 2; ks++) {
            uint32_t a[4][4], b[4][2];
#pragma unroll
            for (int mt = 0; mt < 4; mt++) {
                uint32_t addr = baseA +
                    ((wm + mt * 16 + (lane & 15)) * ASTR +
                     ks * 16 + (lane >> 4) * 8) * 2;
                ldsm_x4(a[mt][0], a[mt][1], a[mt][2], a[mt][3], addr);
            }
#pragma unroll
            for (int nt = 0; nt < 4; nt++) {
                uint32_t addr = baseB +
                    ((wn + nt * 8 + (lane & 7)) * ASTR +
                     ks * 16 + ((lane >> 3) & 1) * 8) * 2;
                ldsm_x2(b[nt][0], b[nt][1], addr);
            }
#pragma unroll
            for (int mt = 0; mt < 4; mt++)
#pragma unroll
                for (int nt = 0; nt < 4; nt++)
                    mma16816(acc[mt][nt], a[mt], b[nt]);
        }
        __syncthreads();
    }

    const int tr = lane >> 2;
    const int tc = (lane & 3) * 2;
#pragma unroll
    for (int mt = 0; mt < 4; mt++) {
#pragma unroll
        for (int nt = 0; nt < 4; nt++) {
            int r = bm + wm + mt * 16 + tr;
            int c = bn + wn + nt * 8 + tc;
            *(float2*)(C + (size_t)r * N + c) =
                make_float2(acc[mt][nt][0], acc[mt][nt][1]);
            *(float2*)(C + (size_t)(r + 8) * N + c) =
                make_float2(acc[mt][nt][2], acc[mt][nt][3]);
        }
    }
}

// ---------------- fp32 -> fp16 convert ---------------------------------------
__global__ __launch_bounds__(256)
void f32to16(const float* __restrict__ s, __half* __restrict__ d) {
    int i = blockIdx.x * 256 + threadIdx.x;
    float4 v = *(const float4*)(s + (size_t)i * 4);
    __half2 h0 = __floats2half2_rn(v.x, v.y);
    __half2 h1 = __floats2half2_rn(v.z, v.w);
    uint2 o;
    o.x = *(const uint32_t*)&h0;
    o.y = *(const uint32_t*)&h1;
    *(uint2*)(d + (size_t)i * 4) = o;
}

// ---------------- RoPE + qkv split into head-major fp16 layout ---------------
__global__ __launch_bounds__(256)
void rope_split(const float* __restrict__ rope) {
    int idx = blockIdx.x * 256 + threadIdx.x;   // < B*L*H*64
    int p = idx & 63;
    int h = (idx >> 6) & 15;
    int l = (idx >> 10) & (CL - 1);
    int b = idx >> 21;

    const float* qkv = g_qkv + (size_t)(b * CL + l) * C3E;
    float s = rope[l * CHD + p * 2 + 0];
    float c = rope[l * CHD + p * 2 + 1];
    int e = h * CHD + 2 * p;
    float q0 = qkv[e],          q1 = qkv[e + 1];
    float k0 = qkv[CE + e],     k1 = qkv[CE + e + 1];
    float v0 = qkv[2*CE + e],   v1 = qkv[2*CE + e + 1];

    size_t off = ((size_t)(b * CH + h) * CL + l) * CHD + 2 * p;
    *(__half2*)(g_qh + off) = __floats2half2_rn(q0 * c - q1 * s, q1 * c + q0 * s);
    *(__half2*)(g_kh + off) = __floats2half2_rn(k0 * c - k1 * s, k1 * c + k0 * s);
    *(__half2*)(g_vh + off) = __floats2half2_rn(v0, v1);
}

// ---------------- causal flash attention (HMMA fp16, fp32 accum) -------------
#define FBQ 64
#define FBK 64
#define FSTR 136   // halves per smem row (128 + 8 pad)
#define FLASH_SMEM (3 * 64 * FSTR * 2)   // 52224 B

__global__ __launch_bounds__(128)
void flash_mma() {
    extern __shared__ __half smh[];
    __half* Qs = smh;                 // [64][136]
    __half* Ks = Qs + 64 * FSTR;
    __half* Vs = Ks + 64 * FSTR;

    const int qt   = gridDim.x - 1 - blockIdx.x;   // long CTAs first
    const int bh   = blockIdx.y;
    const int tid  = threadIdx.x;
    const int lane = tid & 31;
    const int wq   = tid >> 5;        // warp -> q rows [wq*16, wq*16+16)
    const float SCALE2 = 0.08838834764831845f * 1.4426950408889634f; // scale*log2e

    const uint32_t sQ = smem_u32(Qs), sK = smem_u32(Ks), sV = smem_u32(Vs);
    const __half* qbase = g_qh + (size_t)bh * CL * CHD + (size_t)qt * FBQ * CHD;
    const __half* kbase = g_kh + (size_t)bh * CL * CHD;
    const __half* vbase = g_vh + (size_t)bh * CL * CHD;

    // load Q tile (64 x 128 fp16 = 1024 16B chunks; 8 per thread)
#pragma unroll
    for (int t = 0; t < 8; t++) {
        int id = t * 128 + tid;
        int row = id >> 4, col = (id & 15) * 8;
        cp16(sQ + (row * FSTR + col) * 2, qbase + (size_t)row * CHD + col);
    }
    CP_COMMIT();
    CP_WAIT0();
    __syncthreads();

    // Q fragments in registers for the whole kernel
    uint32_t qf[8][4];
#pragma unroll
    for (int ks = 0; ks < 8; ks++) {
        uint32_t addr = sQ + ((wq * 16 + (lane & 15)) * FSTR
                              + ks * 16 + (lane >> 4) * 8) * 2;
        ldsm_x4(qf[ks][0], qf[ks][1], qf[ks][2], qf[ks][3], addr);
    }

    float o[16][4];
#pragma unroll
    for (int nt = 0; nt < 16; nt++)
#pragma unroll
        for (int i = 0; i < 4; i++) o[nt][i] = 0.f;
    float M0 = -1e30f, M1 = -1e30f, L0 = 0.f, L1 = 0.f;

    const int qg0 = qt * FBQ + wq * 16 + (lane >> 2);   // row0 global q index

    for (int kt = 0; kt <= qt; kt++) {
        const __half* kp = kbase + (size_t)kt * FBK * CHD;
        const __half* vp = vbase + (size_t)kt * FBK * CHD;
#pragma unroll
        for (int t = 0; t < 8; t++) {
            int id = t * 128 + tid;
            int row = id >> 4, col = (id & 15) * 8;
            cp16(sK + (row * FSTR + col) * 2, kp + (size_t)row * CHD + col);
            cp16(sV + (row * FSTR + col) * 2, vp + (size_t)row * CHD + col);
        }
        CP_COMMIT();
        CP_WAIT0();
        __syncthreads();

        // S = Q K^T  (16 x 64 per warp, fp32 accum)
        float s[8][4];
#pragma unroll
        for (int j = 0; j < 8; j++)
#pragma unroll
            for (int i = 0; i < 4; i++) s[j][i] = 0.f;
#pragma unroll
        for (int ks = 0; ks < 8; ks++) {
#pragma unroll
            for (int jn = 0; jn < 4; jn++) {
                uint32_t r0, r1, r2, r3;
                uint32_t addr = sK + ((jn * 16 + (lane & 15)) * FSTR
                                      + ks * 16 + (lane >> 4) * 8) * 2;
                ldsm_x4(r0, r1, r2, r3, addr);
                uint32_t b0[2] = {r0, r2}, b1[2] = {r1, r3};
                mma16816(s[2 * jn],     qf[ks], b0);
                mma16816(s[2 * jn + 1], qf[ks], b1);
            }
        }

        // causal mask (diagonal tile only)
        if (kt == qt) {
#pragma unroll
            for (int j = 0; j < 8; j++) {
                int kg = kt * FBK + j * 8 + (lane & 3) * 2;
                if (kg     > qg0)     s[j][0] = -1e30f;
                if (kg + 1 > qg0)     s[j][1] = -1e30f;
                if (kg     > qg0 + 8) s[j][2] = -1e30f;
                if (kg + 1 > qg0 + 8) s[j][3] = -1e30f;
            }
        }

        // online softmax (rows tr / tr+8), scaled log2 domain
        float mx0 = -1e30f, mx1 = -1e30f;
#pragma unroll
        for (int j = 0; j < 8; j++) {
            mx0 = fmaxf(mx0, fmaxf(s[j][0], s[j][1]));
            mx1 = fmaxf(mx1, fmaxf(s[j][2], s[j][3]));
        }
        mx0 = fmaxf(mx0, __shfl_xor_sync(0xffffffffu, mx0, 1));
        mx0 = fmaxf(mx0, __shfl_xor_sync(0xffffffffu, mx0, 2));
        mx1 = fmaxf(mx1, __shfl_xor_sync(0xffffffffu, mx1, 1));
        mx1 = fmaxf(mx1, __shfl_xor_sync(0xffffffffu, mx1, 2));

        float Mn0 = fmaxf(M0, mx0 * SCALE2);
        float Mn1 = fmaxf(M1, mx1 * SCALE2);
        float a0 = ex2f(M0 - Mn0);
        float a1 = ex2f(M1 - Mn1);
        M0 = Mn0; M1 = Mn1;

        float sum0 = 0.f, sum1 = 0.f;
#pragma unroll
        for (int j = 0; j < 8; j++) {
            s[j][0] = ex2f(fmaf(s[j][0], SCALE2, -Mn0));
            s[j][1] = ex2f(fmaf(s[j][1], SCALE2, -Mn0));
            s[j][2] = ex2f(fmaf(s[j][2], SCALE2, -Mn1));
            s[j][3] = ex2f(fmaf(s[j][3], SCALE2, -Mn1));
            sum0 += s[j][0] + s[j][1];
            sum1 += s[j][2] + s[j][3];
        }
        sum0 += __shfl_xor_sync(0xffffffffu, sum0, 1);
        sum0 += __shfl_xor_sync(0xffffffffu, sum0, 2);
        sum1 += __shfl_xor_sync(0xffffffffu, sum1, 1);
        sum1 += __shfl_xor_sync(0xffffffffu, sum1, 2);
        L0 = L0 * a0 + sum0;
        L1 = L1 * a1 + sum1;

#pragma unroll
        for (int nt = 0; nt < 16; nt++) {
            o[nt][0] *= a0; o[nt][1] *= a0;
            o[nt][2] *= a1; o[nt][3] *= a1;
        }

        // P fragments (fp16) from S accumulators (C->A layout identity)
        uint32_t pf[4][4];
#pragma unroll
        for (int jk = 0; jk < 4; jk++) {
            __half2 h0 = __floats2half2_rn(s[2*jk][0],   s[2*jk][1]);
            __half2 h1 = __floats2half2_rn(s[2*jk][2],   s[2*jk][3]);
            __half2 h2 = __floats2half2_rn(s[2*jk+1][0], s[2*jk+1][1]);
            __half2 h3 = __floats2half2_rn(s[2*jk+1][2], s[2*jk+1][3]);
            pf[jk][0] = *(const uint32_t*)&h0;
            pf[jk][1] = *(const uint32_t*)&h1;
            pf[jk][2] = *(const uint32_t*)&h2;
            pf[jk][3] = *(const uint32_t*)&h3;
        }

        // O += P @ V  (V^T fragments via ldmatrix.trans)
#pragma unroll
        for (int jk = 0; jk < 4; jk++) {
#pragma unroll
            for (int dn = 0; dn < 8; dn++) {
                uint32_t r0, r1, r2, r3;
                uint32_t addr = sV + ((jk * 16 + (lane & 15)) * FSTR
                                      + dn * 16 + (lane >> 4) * 8) * 2;
                ldsm_x4t(r0, r1, r2, r3, addr);
                uint32_t b0[2] = {r0, r1}, b1[2] = {r2, r3};
                mma16816(o[2 * dn],     pf[jk], b0);
                mma16816(o[2 * dn + 1], pf[jk], b1);
            }
        }
        __syncthreads();
    }

    // epilogue: fp16 into g_yh[b, q, h*128 + d]
    const int b = bh >> 4, h = bh & 15;
    const float inv0 = 1.f / L0, inv1 = 1.f / L1;
    __half* dst0 = g_yh + (size_t)(b * CL + qg0) * CE + h * CHD;
    __half* dst1 = dst0 + (size_t)8 * CE;
#pragma unroll
    for (int nt = 0; nt < 16; nt++) {
        int d = nt * 8 + (lane & 3) * 2;
        __half2 h0 = __floats2half2_rn(o[nt][0] * inv0, o[nt][1] * inv0);
        __half2 h1 = __floats2half2_rn(o[nt][2] * inv1, o[nt][3] * inv1);
        *(__half2*)(dst0 + d) = h0;
        *(__half2*)(dst1 + d) = h1;
    }
}

// ---------------- host launcher ---------------------------------------------
extern "C" void kernel_launch(void* const* d_in, const int* in_sizes, int n_in,
                              void* d_out, int out_size) {
    const float* x      = (const float*)d_in[0];
    const float* rope   = (const float*)d_in[1];
    const float* w_attn = (const float*)d_in[2];
    const float* w_proj = (const float*)d_in[3];
    float* out = (float*)d_out;

    float *qkv_p;
    __half *xh_p, *wah_p, *wph_p, *yh_p;
    cudaGetSymbolAddress((void**)&qkv_p, g_qkv);
    cudaGetSymbolAddress((void**)&xh_p,  g_xh);
    cudaGetSymbolAddress((void**)&wah_p, g_wah);
    cudaGetSymbolAddress((void**)&wph_p, g_wph);
    cudaGetSymbolAddress((void**)&yh_p,  g_yh);

    static bool attr_set = false;
    if (!attr_set) {
        cudaFuncSetAttribute(flash_mma, cudaFuncAttributeMaxDynamicSharedMemorySize,
                             FLASH_SMEM);
        attr_set = true;
    }

    // 0) fp32 -> fp16 converts
    f32to16<<<(CM * CE / 4) / 256, 256>>>(x, xh_p);
    f32to16<<<(C3E * CE / 4) / 256, 256>>>(w_attn, wah_p);
    f32to16<<<(CE * CE / 4) / 256, 256>>>(w_proj, wph_p);

    // 1) qkv = x @ w_attn^T   [4096, 6144]  (HMMA fp16)
    hgemm_mma<<<dim3(C3E / BN, CM / BM), 256>>>(xh_p, wah_p, qkv_p, CM, C3E, CE);

    // 2) rope + split into head-major fp16 q/k/v
    rope_split<<<(CB * CL * CH * 64) / 256, 256>>>(rope);

    // 3) causal flash attention (HMMA) -> g_yh (fp16)
    flash_mma<<<dim3(CL / FBQ, CB * CH), 128, FLASH_SMEM>>>();

    // 4) out = y @ w_proj^T   [4096, 2048]  (HMMA fp16)
    hgemm_mma<<<dim3(CE / BN, CM / BM), 256>>>(yh_p, wph_p, out, CM, CE, CE);
}

// round 7
// speedup vs baseline: 5.8036x; 1.0011x over previous
#include <cuda_runtime.h>
#include <cuda_fp16.h>
#include <cstdint>

#define CB 2
#define CL 2048
#define CE 2048
#define CH 16
#define CHD 128
#define CM (CB*CL)      // 4096
#define C3E (3*CE)      // 6144

// ---------------- scratch (device globals; no allocations allowed) ----------
static __device__ float  g_qkv[(size_t)CM * C3E];        // [B*L, 3E] fp32
static __device__ __half g_qh[(size_t)CB*CH*CL*CHD];     // [b,h,l,d] fp16
static __device__ __half g_kh[(size_t)CB*CH*CL*CHD];
static __device__ __half g_vh[(size_t)CB*CH*CL*CHD];
static __device__ __half g_xh[(size_t)CM * CE];          // x in fp16
static __device__ __half g_wah[(size_t)C3E * CE];        // w_attn fp16
static __device__ __half g_wph[(size_t)CE * CE];         // w_proj fp16
static __device__ __half g_yh[(size_t)CM * CE];          // attention out fp16

// ---------------- PTX helpers -------------------------------------------------
__device__ __forceinline__ uint32_t smem_u32(const void* p) {
    uint32_t a;
    asm("{ .reg .u64 t; cvta.to.shared.u64 t, %1; cvt.u32.u64 %0, t; }"
        : "=r"(a) : "l"(p));
    return a;
}
__device__ __forceinline__ void cp16(uint32_t dst, const void* src) {
    asm volatile("cp.async.cg.shared.global [%0], [%1], 16;"
                 :: "r"(dst), "l"(src));
}
#define CP_COMMIT() asm volatile("cp.async.commit_group;" ::: "memory")
#define CP_WAIT0()  asm volatile("cp.async.wait_group 0;" ::: "memory")

__device__ __forceinline__ void ldsm_x4(uint32_t& r0, uint32_t& r1,
                                        uint32_t& r2, uint32_t& r3, uint32_t a) {
    asm volatile("ldmatrix.sync.aligned.m8n8.x4.shared.b16 {%0,%1,%2,%3}, [%4];"
                 : "=r"(r0), "=r"(r1), "=r"(r2), "=r"(r3) : "r"(a));
}
__device__ __forceinline__ void ldsm_x4t(uint32_t& r0, uint32_t& r1,
                                         uint32_t& r2, uint32_t& r3, uint32_t a) {
    asm volatile("ldmatrix.sync.aligned.m8n8.x4.trans.shared.b16 {%0,%1,%2,%3}, [%4];"
                 : "=r"(r0), "=r"(r1), "=r"(r2), "=r"(r3) : "r"(a));
}
__device__ __forceinline__ void ldsm_x2(uint32_t& r0, uint32_t& r1, uint32_t a) {
    asm volatile("ldmatrix.sync.aligned.m8n8.x2.shared.b16 {%0,%1}, [%2];"
                 : "=r"(r0), "=r"(r1) : "r"(a));
}
__device__ __forceinline__ void mma16816(float* c, const uint32_t* a,
                                         const uint32_t* b) {
    asm volatile("mma.sync.aligned.m16n8k16.row.col.f32.f16.f16.f32 "
                 "{%0,%1,%2,%3}, {%4,%5,%6,%7}, {%8,%9}, {%0,%1,%2,%3};"
                 : "+f"(c[0]), "+f"(c[1]), "+f"(c[2]), "+f"(c[3])
                 : "r"(a[0]), "r"(a[1]), "r"(a[2]), "r"(a[3]),
                   "r"(b[0]), "r"(b[1]));
}
__device__ __forceinline__ float ex2f(float x) {
    float y;
    asm("ex2.approx.ftz.f32 %0, %1;" : "=f"(y) : "f"(x));
    return y;
}

// ---------------- HMMA fp16 GEMM: C[M,N] = A[M,K] * B[N,K]^T (fp32 out) -----
#define BM 128
#define BN 128
#define BK 32
#define ASTR 40

__global__ __launch_bounds__(256, 2)
void hgemm_mma(const __half* __restrict__ A, const __half* __restrict__ B,
               float* __restrict__ C, int M, int N, int K) {
    __shared__ __align__(16) __half As[2][BM * ASTR];
    __shared__ __align__(16) __half Bs[2][BN * ASTR];

    const int tid  = threadIdx.x;
    const int lane = tid & 31;
    const int wid  = tid >> 5;
    const int wm   = (wid >> 2) * 64;
    const int wn   = (wid & 3) * 32;
    const int bm   = blockIdx.y * BM;
    const int bn   = blockIdx.x * BN;

    const __half* Ab = A + (size_t)bm * K;
    const __half* Bb = B + (size_t)bn * K;

    float acc[4][4][4];
#pragma unroll
    for (int mt = 0; mt < 4; mt++)
#pragma unroll
        for (int nt = 0; nt < 4; nt++)
#pragma unroll
            for (int i = 0; i < 4; i++) acc[mt][nt][i] = 0.f;

    const int r0c = tid >> 1;
    const int c0c = (tid & 1) * 2;
    const uint32_t smA = smem_u32(As);
    const uint32_t smB = smem_u32(Bs);

    auto load_stage = [&](int s, int kc) {
        const __half* ap = Ab + kc * BK;
        const __half* bp = Bb + kc * BK;
        uint32_t da = smA + (uint32_t)(s * BM * ASTR * 2);
        uint32_t db = smB + (uint32_t)(s * BN * ASTR * 2);
#pragma unroll
        for (int cc = 0; cc < 2; cc++) {
            int col8 = (c0c + cc) * 8;
            cp16(da + (r0c * ASTR + col8) * 2, ap + (size_t)r0c * K + col8);
            cp16(db + (r0c * ASTR + col8) * 2, bp + (size_t)r0c * K + col8);
        }
    };

    const int nk = K / BK;
    load_stage(0, 0);
    CP_COMMIT();

    for (int kc = 0; kc < nk; kc++) {
        const int s = kc & 1;
        CP_WAIT0();
        __syncthreads();
        if (kc + 1 < nk) {
            load_stage(s ^ 1, kc + 1);
            CP_COMMIT();
        }

        const uint32_t baseA = smA + (uint32_t)(s * BM * ASTR * 2);
        const uint32_t baseB = smB + (uint32_t)(s * BN * ASTR * 2);
#pragma unroll
        for (int ks = 0; ks < 2; ks++) {
            uint32_t a[4][4], b[4][2];
#pragma unroll
            for (int mt = 0; mt < 4; mt++) {
                uint32_t addr = baseA +
                    ((wm + mt * 16 + (lane & 15)) * ASTR +
                     ks * 16 + (lane >> 4) * 8) * 2;
                ldsm_x4(a[mt][0], a[mt][1], a[mt][2], a[mt][3], addr);
            }
#pragma unroll
            for (int nt = 0; nt < 4; nt++) {
                uint32_t addr = baseB +
                    ((wn + nt * 8 + (lane & 7)) * ASTR +
                     ks * 16 + ((lane >> 3) & 1) * 8) * 2;
                ldsm_x2(b[nt][0], b[nt][1], addr);
            }
#pragma unroll
            for (int mt = 0; mt < 4; mt++)
#pragma unroll
                for (int nt = 0; nt < 4; nt++)
                    mma16816(acc[mt][nt], a[mt], b[nt]);
        }
        __syncthreads();
    }

    const int tr = lane >> 2;
    const int tc = (lane & 3) * 2;
#pragma unroll
    for (int mt = 0; mt < 4; mt++) {
#pragma unroll
        for (int nt = 0; nt < 4; nt++) {
            int r = bm + wm + mt * 16 + tr;
            int c = bn + wn + nt * 8 + tc;
            *(float2*)(C + (size_t)r * N + c) =
                make_float2(acc[mt][nt][0], acc[mt][nt][1]);
            *(float2*)(C + (size_t)(r + 8) * N + c) =
                make_float2(acc[mt][nt][2], acc[mt][nt][3]);
        }
    }
}

// ---------------- fp32 -> fp16 convert ---------------------------------------
__global__ __launch_bounds__(256)
void f32to16(const float* __restrict__ s, __half* __restrict__ d) {
    int i = blockIdx.x * 256 + threadIdx.x;
    float4 v = *(const float4*)(s + (size_t)i * 4);
    __half2 h0 = __floats2half2_rn(v.x, v.y);
    __half2 h1 = __floats2half2_rn(v.z, v.w);
    uint2 o;
    o.x = *(const uint32_t*)&h0;
    o.y = *(const uint32_t*)&h1;
    *(uint2*)(d + (size_t)i * 4) = o;
}

// ---------------- RoPE + qkv split into head-major fp16 layout ---------------
__global__ __launch_bounds__(256)
void rope_split(const float* __restrict__ rope) {
    int idx = blockIdx.x * 256 + threadIdx.x;   // < B*L*H*64
    int p = idx & 63;
    int h = (idx >> 6) & 15;
    int l = (idx >> 10) & (CL - 1);
    int b = idx >> 21;

    const float* qkv = g_qkv + (size_t)(b * CL + l) * C3E;
    float s = rope[l * CHD + p * 2 + 0];
    float c = rope[l * CHD + p * 2 + 1];
    int e = h * CHD + 2 * p;
    float q0 = qkv[e],          q1 = qkv[e + 1];
    float k0 = qkv[CE + e],     k1 = qkv[CE + e + 1];
    float v0 = qkv[2*CE + e],   v1 = qkv[2*CE + e + 1];

    size_t off = ((size_t)(b * CH + h) * CL + l) * CHD + 2 * p;
    *(__half2*)(g_qh + off) = __floats2half2_rn(q0 * c - q1 * s, q1 * c + q0 * s);
    *(__half2*)(g_kh + off) = __floats2half2_rn(k0 * c - k1 * s, k1 * c + k0 * s);
    *(__half2*)(g_vh + off) = __floats2half2_rn(v0, v1);
}

// ---------------- causal flash attention (HMMA fp16, fp32 accum) -------------
#define FBQ 64
#define FBK 64
#define FSTR 136   // halves per smem row (128 + 8 pad)
#define FLASH_SMEM (3 * 64 * FSTR * 2)   // 52224 B

__global__ __launch_bounds__(128)
void flash_mma() {
    extern __shared__ __half smh[];
    __half* Qs = smh;                 // [64][136]
    __half* Ks = Qs + 64 * FSTR;
    __half* Vs = Ks + 64 * FSTR;

    const int qt   = gridDim.x - 1 - blockIdx.x;   // long CTAs first
    const int bh   = blockIdx.y;
    const int tid  = threadIdx.x;
    const int lane = tid & 31;
    const int wq   = tid >> 5;        // warp -> q rows [wq*16, wq*16+16)
    const float SCALE2 = 0.08838834764831845f * 1.4426950408889634f; // scale*log2e

    const uint32_t sQ = smem_u32(Qs), sK = smem_u32(Ks), sV = smem_u32(Vs);
    const __half* qbase = g_qh + (size_t)bh * CL * CHD + (size_t)qt * FBQ * CHD;
    const __half* kbase = g_kh + (size_t)bh * CL * CHD;
    const __half* vbase = g_vh + (size_t)bh * CL * CHD;

    // load Q tile (64 x 128 fp16 = 1024 16B chunks; 8 per thread)
#pragma unroll
    for (int t = 0; t < 8; t++) {
        int id = t * 128 + tid;
        int row = id >> 4, col = (id & 15) * 8;
        cp16(sQ + (row * FSTR + col) * 2, qbase + (size_t)row * CHD + col);
    }
    CP_COMMIT();
    CP_WAIT0();
    __syncthreads();

    // Q fragments in registers for the whole kernel
    uint32_t qf[8][4];
#pragma unroll
    for (int ks = 0; ks < 8; ks++) {
        uint32_t addr = sQ + ((wq * 16 + (lane & 15)) * FSTR
                              + ks * 16 + (lane >> 4) * 8) * 2;
        ldsm_x4(qf[ks][0], qf[ks][1], qf[ks][2], qf[ks][3], addr);
    }

    float o[16][4];
#pragma unroll
    for (int nt = 0; nt < 16; nt++)
#pragma unroll
        for (int i = 0; i < 4; i++) o[nt][i] = 0.f;
    float M0 = -1e30f, M1 = -1e30f, L0 = 0.f, L1 = 0.f;

    const int qg0 = qt * FBQ + wq * 16 + (lane >> 2);   // row0 global q index

    for (int kt = 0; kt <= qt; kt++) {
        const __half* kp = kbase + (size_t)kt * FBK * CHD;
        const __half* vp = vbase + (size_t)kt * FBK * CHD;
#pragma unroll
        for (int t = 0; t < 8; t++) {
            int id = t * 128 + tid;
            int row = id >> 4, col = (id & 15) * 8;
            cp16(sK + (row * FSTR + col) * 2, kp + (size_t)row * CHD + col);
            cp16(sV + (row * FSTR + col) * 2, vp + (size_t)row * CHD + col);
        }
        CP_COMMIT();
        CP_WAIT0();
        __syncthreads();

        // S = Q K^T  (16 x 64 per warp, fp32 accum)
        float s[8][4];
#pragma unroll
        for (int j = 0; j < 8; j++)
#pragma unroll
            for (int i = 0; i < 4; i++) s[j][i] = 0.f;
#pragma unroll
        for (int ks = 0; ks < 8; ks++) {
#pragma unroll
            for (int jn = 0; jn < 4; jn++) {
                uint32_t r0, r1, r2, r3;
                uint32_t addr = sK + ((jn * 16 + (lane & 15)) * FSTR
                                      + ks * 16 + (lane >> 4) * 8) * 2;
                ldsm_x4(r0, r1, r2, r3, addr);
                uint32_t b0[2] = {r0, r2}, b1[2] = {r1, r3};
                mma16816(s[2 * jn],     qf[ks], b0);
                mma16816(s[2 * jn + 1], qf[ks], b1);
            }
        }

        // causal mask (diagonal tile only)
        if (kt == qt) {
#pragma unroll
            for (int j = 0; j < 8; j++) {
                int kg = kt * FBK + j * 8 + (lane & 3) * 2;
                if (kg     > qg0)     s[j][0] = -1e30f;
                if (kg + 1 > qg0)     s[j][1] = -1e30f;
                if (kg     > qg0 + 8) s[j][2] = -1e30f;
                if (kg + 1 > qg0 + 8) s[j][3] = -1e30f;
            }
        }

        // online softmax (rows tr / tr+8), scaled log2 domain
        float mx0 = -1e30f, mx1 = -1e30f;
#pragma unroll
        for (int j = 0; j < 8; j++) {
            mx0 = fmaxf(mx0, fmaxf(s[j][0], s[j][1]));
            mx1 = fmaxf(mx1, fmaxf(s[j][2], s[j][3]));
        }
        mx0 = fmaxf(mx0, __shfl_xor_sync(0xffffffffu, mx0, 1));
        mx0 = fmaxf(mx0, __shfl_xor_sync(0xffffffffu, mx0, 2));
        mx1 = fmaxf(mx1, __shfl_xor_sync(0xffffffffu, mx1, 1));
        mx1 = fmaxf(mx1, __shfl_xor_sync(0xffffffffu, mx1, 2));

        float Mn0 = fmaxf(M0, mx0 * SCALE2);
        float Mn1 = fmaxf(M1, mx1 * SCALE2);
        float a0 = ex2f(M0 - Mn0);
        float a1 = ex2f(M1 - Mn1);
        M0 = Mn0; M1 = Mn1;

        float sum0 = 0.f, sum1 = 0.f;
#pragma unroll
        for (int j = 0; j < 8; j++) {
            s[j][0] = ex2f(fmaf(s[j][0], SCALE2, -Mn0));
            s[j][1] = ex2f(fmaf(s[j][1], SCALE2, -Mn0));
            s[j][2] = ex2f(fmaf(s[j][2], SCALE2, -Mn1));
            s[j][3] = ex2f(fmaf(s[j][3], SCALE2, -Mn1));
            sum0 += s[j][0] + s[j][1];
            sum1 += s[j][2] + s[j][3];
        }
        sum0 += __shfl_xor_sync(0xffffffffu, sum0, 1);
        sum0 += __shfl_xor_sync(0xffffffffu, sum0, 2);
        sum1 += __shfl_xor_sync(0xffffffffu, sum1, 1);
        sum1 += __shfl_xor_sync(0xffffffffu, sum1, 2);
        L0 = L0 * a0 + sum0;
        L1 = L1 * a1 + sum1;

#pragma unroll
        for (int nt = 0; nt < 16; nt++) {
            o[nt][0] *= a0; o[nt][1] *= a0;
            o[nt][2] *= a1; o[nt][3] *= a1;
        }

        // P fragments (fp16) from S accumulators (C->A layout identity)
        uint32_t pf[4][4];
#pragma unroll
        for (int jk = 0; jk < 4; jk++) {
            __half2 h0 = __floats2half2_rn(s[2*jk][0],   s[2*jk][1]);
            __half2 h1 = __floats2half2_rn(s[2*jk][2],   s[2*jk][3]);
            __half2 h2 = __floats2half2_rn(s[2*jk+1][0], s[2*jk+1][1]);
            __half2 h3 = __floats2half2_rn(s[2*jk+1][2], s[2*jk+1][3]);
            pf[jk][0] = *(const uint32_t*)&h0;
            pf[jk][1] = *(const uint32_t*)&h1;
            pf[jk][2] = *(const uint32_t*)&h2;
            pf[jk][3] = *(const uint32_t*)&h3;
        }

        // O += P @ V  (V^T fragments via ldmatrix.trans)
#pragma unroll
        for (int jk = 0; jk < 4; jk++) {
#pragma unroll
            for (int dn = 0; dn < 8; dn++) {
                uint32_t r0, r1, r2, r3;
                uint32_t addr = sV + ((jk * 16 + (lane & 15)) * FSTR
                                      + dn * 16 + (lane >> 4) * 8) * 2;
                ldsm_x4t(r0, r1, r2, r3, addr);
                uint32_t b0[2] = {r0, r1}, b1[2] = {r2, r3};
                mma16816(o[2 * dn],     pf[jk], b0);
                mma16816(o[2 * dn + 1], pf[jk], b1);
            }
        }
        __syncthreads();
    }

    // epilogue: fp16 into g_yh[b, q, h*128 + d]
    const int b = bh >> 4, h = bh & 15;
    const float inv0 = 1.f / L0, inv1 = 1.f / L1;
    __half* dst0 = g_yh + (size_t)(b * CL + qg0) * CE + h * CHD;
    __half* dst1 = dst0 + (size_t)8 * CE;
#pragma unroll
    for (int nt = 0; nt < 16; nt++) {
        int d = nt * 8 + (lane & 3) * 2;
        __half2 h0 = __floats2half2_rn(o[nt][0] * inv0, o[nt][1] * inv0);
        __half2 h1 = __floats2half2_rn(o[nt][2] * inv1, o[nt][3] * inv1);
        *(__half2*)(dst0 + d) = h0;
        *(__half2*)(dst1 + d) = h1;
    }
}

// ---------------- host launcher ---------------------------------------------
extern "C" void kernel_launch(void* const* d_in, const int* in_sizes, int n_in,
                              void* d_out, int out_size) {
    const float* x      = (const float*)d_in[0];
    const float* rope   = (const float*)d_in[1];
    const float* w_attn = (const float*)d_in[2];
    const float* w_proj = (const float*)d_in[3];
    float* out = (float*)d_out;

    float *qkv_p;
    __half *xh_p, *wah_p, *wph_p, *yh_p;
    cudaGetSymbolAddress((void**)&qkv_p, g_qkv);
    cudaGetSymbolAddress((void**)&xh_p,  g_xh);
    cudaGetSymbolAddress((void**)&wah_p, g_wah);
    cudaGetSymbolAddress((void**)&wph_p, g_wph);
    cudaGetSymbolAddress((void**)&yh_p,  g_yh);

    static bool attr_set = false;
    if (!attr_set) {
        cudaFuncSetAttribute(flash_mma, cudaFuncAttributeMaxDynamicSharedMemorySize,
                             FLASH_SMEM);
        attr_set = true;
    }

    // 0) fp32 -> fp16 converts
    f32to16<<<(CM * CE / 4) / 256, 256>>>(x, xh_p);
    f32to16<<<(C3E * CE / 4) / 256, 256>>>(w_attn, wah_p);
    f32to16<<<(CE * CE / 4) / 256, 256>>>(w_proj, wph_p);

    // 1) qkv = x @ w_attn^T   [4096, 6144]  (HMMA fp16)
    hgemm_mma<<<dim3(C3E / BN, CM / BM), 256>>>(xh_p, wah_p, qkv_p, CM, C3E, CE);

    // 2) rope + split into head-major fp16 q/k/v
    rope_split<<<(CB * CL * CH * 64) / 256, 256>>>(rope);

    // 3) causal flash attention (HMMA) -> g_yh (fp16)
    flash_mma<<<dim3(CL / FBQ, CB * CH), 128, FLASH_SMEM>>>();

    // 4) out = y @ w_proj^T   [4096, 2048]  (HMMA fp16)
    hgemm_mma<<<dim3(CE / BN, CM / BM), 256>>>(yh_p, wph_p, out, CM, CE, CE);
}

// round 8
// speedup vs baseline: 6.0261x; 1.0383x over previous
#include <cuda_runtime.h>
#include <cuda_fp16.h>
#include <cstdint>

#define CB 2
#define CL 2048
#define CE 2048
#define CH 16
#define CHD 128
#define CM (CB*CL)      // 4096
#define C3E (3*CE)      // 6144

// ---------------- scratch (device globals; no allocations allowed) ----------
static __device__ float  g_qkv[(size_t)CM * C3E];        // [B*L, 3E] fp32
static __device__ __half g_qh[(size_t)CB*CH*CL*CHD];     // [b,h,l,d] fp16
static __device__ __half g_kh[(size_t)CB*CH*CL*CHD];
static __device__ __half g_vh[(size_t)CB*CH*CL*CHD];
static __device__ __half g_xh[(size_t)CM * CE];          // x in fp16
static __device__ __half g_wah[(size_t)C3E * CE];        // w_attn fp16
static __device__ __half g_wph[(size_t)CE * CE];         // w_proj fp16
static __device__ __half g_yh[(size_t)CM * CE];          // attention out fp16

// ---------------- PTX helpers -------------------------------------------------
__device__ __forceinline__ uint32_t smem_u32(const void* p) {
    uint32_t a;
    asm("{ .reg .u64 t; cvta.to.shared.u64 t, %1; cvt.u32.u64 %0, t; }"
        : "=r"(a) : "l"(p));
    return a;
}
__device__ __forceinline__ void cp16(uint32_t dst, const void* src) {
    asm volatile("cp.async.cg.shared.global [%0], [%1], 16;"
                 :: "r"(dst), "l"(src));
}
#define CP_COMMIT() asm volatile("cp.async.commit_group;" ::: "memory")
#define CP_WAIT(n)  asm volatile("cp.async.wait_group %0;" :: "n"(n) : "memory")

__device__ __forceinline__ void ldsm_x4(uint32_t& r0, uint32_t& r1,
                                        uint32_t& r2, uint32_t& r3, uint32_t a) {
    asm volatile("ldmatrix.sync.aligned.m8n8.x4.shared.b16 {%0,%1,%2,%3}, [%4];"
                 : "=r"(r0), "=r"(r1), "=r"(r2), "=r"(r3) : "r"(a));
}
__device__ __forceinline__ void ldsm_x4t(uint32_t& r0, uint32_t& r1,
                                         uint32_t& r2, uint32_t& r3, uint32_t a) {
    asm volatile("ldmatrix.sync.aligned.m8n8.x4.trans.shared.b16 {%0,%1,%2,%3}, [%4];"
                 : "=r"(r0), "=r"(r1), "=r"(r2), "=r"(r3) : "r"(a));
}
__device__ __forceinline__ void ldsm_x2(uint32_t& r0, uint32_t& r1, uint32_t a) {
    asm volatile("ldmatrix.sync.aligned.m8n8.x2.shared.b16 {%0,%1}, [%2];"
                 : "=r"(r0), "=r"(r1) : "r"(a));
}
__device__ __forceinline__ void mma16816(float* c, const uint32_t* a,
                                         const uint32_t* b) {
    asm volatile("mma.sync.aligned.m16n8k16.row.col.f32.f16.f16.f32 "
                 "{%0,%1,%2,%3}, {%4,%5,%6,%7}, {%8,%9}, {%0,%1,%2,%3};"
                 : "+f"(c[0]), "+f"(c[1]), "+f"(c[2]), "+f"(c[3])
                 : "r"(a[0]), "r"(a[1]), "r"(a[2]), "r"(a[3]),
                   "r"(b[0]), "r"(b[1]));
}
__device__ __forceinline__ float ex2f(float x) {
    float y;
    asm("ex2.approx.ftz.f32 %0, %1;" : "=f"(y) : "f"(x));
    return y;
}

// ---------------- HMMA fp16 GEMM: C[M,N] = A[M,K] * B[N,K]^T (fp32 out) -----
// 128x128 CTA tile, BK=32, 4-stage cp.async pipeline, 8 warps (2x4).
#define BM 128
#define BN 128
#define BK 32
#define ASTR 40
#define STAGES 4
#define ASTAGE (BM * ASTR)                    // halves
#define STG_HALVES ((BM + BN) * ASTR)
#define GEMM_SMEM (STAGES * STG_HALVES * 2)   // 81920 B

__global__ __launch_bounds__(256, 2)
void hgemm_mma(const __half* __restrict__ A, const __half* __restrict__ B,
               float* __restrict__ C, int M, int N, int K) {
    extern __shared__ __half smg[];
    const uint32_t smBase = smem_u32(smg);

    const int tid  = threadIdx.x;
    const int lane = tid & 31;
    const int wid  = tid >> 5;
    const int wm   = (wid >> 2) * 64;
    const int wn   = (wid & 3) * 32;
    const int bm   = blockIdx.y * BM;
    const int bn   = blockIdx.x * BN;

    const __half* Ab = A + (size_t)bm * K;
    const __half* Bb = B + (size_t)bn * K;

    float acc[4][4][4];
#pragma unroll
    for (int mt = 0; mt < 4; mt++)
#pragma unroll
        for (int nt = 0; nt < 4; nt++)
#pragma unroll
            for (int i = 0; i < 4; i++) acc[mt][nt][i] = 0.f;

    const int r0c = tid >> 1;            // row 0..127
    const int c0c = (tid & 1) * 2;       // 16B-chunk col base

    auto load_stage = [&](int s, int kc) {
        const __half* ap = Ab + kc * BK;
        const __half* bp = Bb + kc * BK;
        uint32_t da = smBase + (uint32_t)(s * STG_HALVES) * 2;
        uint32_t db = da + ASTAGE * 2;
#pragma unroll
        for (int cc = 0; cc < 2; cc++) {
            int col8 = (c0c + cc) * 8;
            cp16(da + (r0c * ASTR + col8) * 2, ap + (size_t)r0c * K + col8);
            cp16(db + (r0c * ASTR + col8) * 2, bp + (size_t)r0c * K + col8);
        }
    };

    const int nk = K / BK;               // 64 (always > STAGES here)
#pragma unroll
    for (int s = 0; s < STAGES - 1; s++) {
        load_stage(s, s);
        CP_COMMIT();
    }

    for (int kc = 0; kc < nk; kc++) {
        // wait for stage kc (keep up to 2 newer groups in flight; shrink in tail)
        if (kc < nk - 2)       CP_WAIT(2);
        else if (kc == nk - 2) CP_WAIT(1);
        else                   CP_WAIT(0);
        __syncthreads();   // publish stage kc; all warps done reading stage kc-1

        if (kc + STAGES - 1 < nk) {
            load_stage((kc + STAGES - 1) & (STAGES - 1), kc + STAGES - 1);
            CP_COMMIT();
        }

        const uint32_t baseA = smBase + (uint32_t)((kc & (STAGES - 1)) * STG_HALVES) * 2;
        const uint32_t baseB = baseA + ASTAGE * 2;
#pragma unroll
        for (int ks = 0; ks < 2; ks++) {
            uint32_t a[4][4], b[4][2];
#pragma unroll
            for (int mt = 0; mt < 4; mt++) {
                uint32_t addr = baseA +
                    ((wm + mt * 16 + (lane & 15)) * ASTR +
                     ks * 16 + (lane >> 4) * 8) * 2;
                ldsm_x4(a[mt][0], a[mt][1], a[mt][2], a[mt][3], addr);
            }
#pragma unroll
            for (int nt = 0; nt < 4; nt++) {
                uint32_t addr = baseB +
                    ((wn + nt * 8 + (lane & 7)) * ASTR +
                     ks * 16 + ((lane >> 3) & 1) * 8) * 2;
                ldsm_x2(b[nt][0], b[nt][1], addr);
            }
#pragma unroll
            for (int mt = 0; mt < 4; mt++)
#pragma unroll
                for (int nt = 0; nt < 4; nt++)
                    mma16816(acc[mt][nt], a[mt], b[nt]);
        }
    }

    const int tr = lane >> 2;
    const int tc = (lane & 3) * 2;
#pragma unroll
    for (int mt = 0; mt < 4; mt++) {
#pragma unroll
        for (int nt = 0; nt < 4; nt++) {
            int r = bm + wm + mt * 16 + tr;
            int c = bn + wn + nt * 8 + tc;
            *(float2*)(C + (size_t)r * N + c) =
                make_float2(acc[mt][nt][0], acc[mt][nt][1]);
            *(float2*)(C + (size_t)(r + 8) * N + c) =
                make_float2(acc[mt][nt][2], acc[mt][nt][3]);
        }
    }
}

// ---------------- fp32 -> fp16 convert ---------------------------------------
__global__ __launch_bounds__(256)
void f32to16(const float* __restrict__ s, __half* __restrict__ d) {
    int i = blockIdx.x * 256 + threadIdx.x;
    float4 v = *(const float4*)(s + (size_t)i * 4);
    __half2 h0 = __floats2half2_rn(v.x, v.y);
    __half2 h1 = __floats2half2_rn(v.z, v.w);
    uint2 o;
    o.x = *(const uint32_t*)&h0;
    o.y = *(const uint32_t*)&h1;
    *(uint2*)(d + (size_t)i * 4) = o;
}

// ---------------- RoPE + qkv split into head-major fp16 layout ---------------
__global__ __launch_bounds__(256)
void rope_split(const float* __restrict__ rope) {
    int idx = blockIdx.x * 256 + threadIdx.x;   // < B*L*H*64
    int p = idx & 63;
    int h = (idx >> 6) & 15;
    int l = (idx >> 10) & (CL - 1);
    int b = idx >> 21;

    const float* qkv = g_qkv + (size_t)(b * CL + l) * C3E;
    float s = rope[l * CHD + p * 2 + 0];
    float c = rope[l * CHD + p * 2 + 1];
    int e = h * CHD + 2 * p;
    float q0 = qkv[e],          q1 = qkv[e + 1];
    float k0 = qkv[CE + e],     k1 = qkv[CE + e + 1];
    float v0 = qkv[2*CE + e],   v1 = qkv[2*CE + e + 1];

    size_t off = ((size_t)(b * CH + h) * CL + l) * CHD + 2 * p;
    *(__half2*)(g_qh + off) = __floats2half2_rn(q0 * c - q1 * s, q1 * c + q0 * s);
    *(__half2*)(g_kh + off) = __floats2half2_rn(k0 * c - k1 * s, k1 * c + k0 * s);
    *(__half2*)(g_vh + off) = __floats2half2_rn(v0, v1);
}

// ---------------- causal flash attention (HMMA fp16, fp32 accum) -------------
#define FBQ 64
#define FBK 64
#define FSTR 136   // halves per smem row (128 + 8 pad)
#define FLASH_SMEM (3 * 64 * FSTR * 2)   // 52224 B

__global__ __launch_bounds__(128)
void flash_mma() {
    extern __shared__ __half smh[];
    __half* Qs = smh;                 // [64][136]
    __half* Ks = Qs + 64 * FSTR;
    __half* Vs = Ks + 64 * FSTR;

    const int qt   = gridDim.x - 1 - blockIdx.x;   // long CTAs first
    const int bh   = blockIdx.y;
    const int tid  = threadIdx.x;
    const int lane = tid & 31;
    const int wq   = tid >> 5;        // warp -> q rows [wq*16, wq*16+16)
    const float SCALE2 = 0.08838834764831845f * 1.4426950408889634f; // scale*log2e

    const uint32_t sQ = smem_u32(Qs), sK = smem_u32(Ks), sV = smem_u32(Vs);
    const __half* qbase = g_qh + (size_t)bh * CL * CHD + (size_t)qt * FBQ * CHD;
    const __half* kbase = g_kh + (size_t)bh * CL * CHD;
    const __half* vbase = g_vh + (size_t)bh * CL * CHD;

    // load Q tile (64 x 128 fp16 = 1024 16B chunks; 8 per thread)
#pragma unroll
    for (int t = 0; t < 8; t++) {
        int id = t * 128 + tid;
        int row = id >> 4, col = (id & 15) * 8;
        cp16(sQ + (row * FSTR + col) * 2, qbase + (size_t)row * CHD + col);
    }
    CP_COMMIT();
    CP_WAIT(0);
    __syncthreads();

    // Q fragments in registers for the whole kernel
    uint32_t qf[8][4];
#pragma unroll
    for (int ks = 0; ks < 8; ks++) {
        uint32_t addr = sQ + ((wq * 16 + (lane & 15)) * FSTR
                              + ks * 16 + (lane >> 4) * 8) * 2;
        ldsm_x4(qf[ks][0], qf[ks][1], qf[ks][2], qf[ks][3], addr);
    }

    float o[16][4];
#pragma unroll
    for (int nt = 0; nt < 16; nt++)
#pragma unroll
        for (int i = 0; i < 4; i++) o[nt][i] = 0.f;
    float M0 = -1e30f, M1 = -1e30f, L0 = 0.f, L1 = 0.f;

    const int qg0 = qt * FBQ + wq * 16 + (lane >> 2);   // row0 global q index

    for (int kt = 0; kt <= qt; kt++) {
        const __half* kp = kbase + (size_t)kt * FBK * CHD;
        const __half* vp = vbase + (size_t)kt * FBK * CHD;
#pragma unroll
        for (int t = 0; t < 8; t++) {
            int id = t * 128 + tid;
            int row = id >> 4, col = (id & 15) * 8;
            cp16(sK + (row * FSTR + col) * 2, kp + (size_t)row * CHD + col);
            cp16(sV + (row * FSTR + col) * 2, vp + (size_t)row * CHD + col);
        }
        CP_COMMIT();
        CP_WAIT(0);
        __syncthreads();

        // S = Q K^T  (16 x 64 per warp, fp32 accum)
        float s[8][4];
#pragma unroll
        for (int j = 0; j < 8; j++)
#pragma unroll
            for (int i = 0; i < 4; i++) s[j][i] = 0.f;
#pragma unroll
        for (int ks = 0; ks < 8; ks++) {
#pragma unroll
            for (int jn = 0; jn < 4; jn++) {
                uint32_t r0, r1, r2, r3;
                uint32_t addr = sK + ((jn * 16 + (lane & 15)) * FSTR
                                      + ks * 16 + (lane >> 4) * 8) * 2;
                ldsm_x4(r0, r1, r2, r3, addr);
                uint32_t b0[2] = {r0, r2}, b1[2] = {r1, r3};
                mma16816(s[2 * jn],     qf[ks], b0);
                mma16816(s[2 * jn + 1], qf[ks], b1);
            }
        }

        // causal mask (diagonal tile only)
        if (kt == qt) {
#pragma unroll
            for (int j = 0; j < 8; j++) {
                int kg = kt * FBK + j * 8 + (lane & 3) * 2;
                if (kg     > qg0)     s[j][0] = -1e30f;
                if (kg + 1 > qg0)     s[j][1] = -1e30f;
                if (kg     > qg0 + 8) s[j][2] = -1e30f;
                if (kg + 1 > qg0 + 8) s[j][3] = -1e30f;
            }
        }

        // online softmax (rows tr / tr+8), scaled log2 domain
        float mx0 = -1e30f, mx1 = -1e30f;
#pragma unroll
        for (int j = 0; j < 8; j++) {
            mx0 = fmaxf(mx0, fmaxf(s[j][0], s[j][1]));
            mx1 = fmaxf(mx1, fmaxf(s[j][2], s[j][3]));
        }
        mx0 = fmaxf(mx0, __shfl_xor_sync(0xffffffffu, mx0, 1));
        mx0 = fmaxf(mx0, __shfl_xor_sync(0xffffffffu, mx0, 2));
        mx1 = fmaxf(mx1, __shfl_xor_sync(0xffffffffu, mx1, 1));
        mx1 = fmaxf(mx1, __shfl_xor_sync(0xffffffffu, mx1, 2));

        float Mn0 = fmaxf(M0, mx0 * SCALE2);
        float Mn1 = fmaxf(M1, mx1 * SCALE2);
        float a0 = ex2f(M0 - Mn0);
        float a1 = ex2f(M1 - Mn1);
        M0 = Mn0; M1 = Mn1;

        float sum0 = 0.f, sum1 = 0.f;
#pragma unroll
        for (int j = 0; j < 8; j++) {
            s[j][0] = ex2f(fmaf(s[j][0], SCALE2, -Mn0));
            s[j][1] = ex2f(fmaf(s[j][1], SCALE2, -Mn0));
            s[j][2] = ex2f(fmaf(s[j][2], SCALE2, -Mn1));
            s[j][3] = ex2f(fmaf(s[j][3], SCALE2, -Mn1));
            sum0 += s[j][0] + s[j][1];
            sum1 += s[j][2] + s[j][3];
        }
        sum0 += __shfl_xor_sync(0xffffffffu, sum0, 1);
        sum0 += __shfl_xor_sync(0xffffffffu, sum0, 2);
        sum1 += __shfl_xor_sync(0xffffffffu, sum1, 1);
        sum1 += __shfl_xor_sync(0xffffffffu, sum1, 2);
        L0 = L0 * a0 + sum0;
        L1 = L1 * a1 + sum1;

#pragma unroll
        for (int nt = 0; nt < 16; nt++) {
            o[nt][0] *= a0; o[nt][1] *= a0;
            o[nt][2] *= a1; o[nt][3] *= a1;
        }

        // P fragments (fp16) from S accumulators (C->A layout identity)
        uint32_t pf[4][4];
#pragma unroll
        for (int jk = 0; jk < 4; jk++) {
            __half2 h0 = __floats2half2_rn(s[2*jk][0],   s[2*jk][1]);
            __half2 h1 = __floats2half2_rn(s[2*jk][2],   s[2*jk][3]);
            __half2 h2 = __floats2half2_rn(s[2*jk+1][0], s[2*jk+1][1]);
            __half2 h3 = __floats2half2_rn(s[2*jk+1][2], s[2*jk+1][3]);
            pf[jk][0] = *(const uint32_t*)&h0;
            pf[jk][1] = *(const uint32_t*)&h1;
            pf[jk][2] = *(const uint32_t*)&h2;
            pf[jk][3] = *(const uint32_t*)&h3;
        }

        // O += P @ V  (V^T fragments via ldmatrix.trans)
#pragma unroll
        for (int jk = 0; jk < 4; jk++) {
#pragma unroll
            for (int dn = 0; dn < 8; dn++) {
                uint32_t r0, r1, r2, r3;
                uint32_t addr = sV + ((jk * 16 + (lane & 15)) * FSTR
                                      + dn * 16 + (lane >> 4) * 8) * 2;
                ldsm_x4t(r0, r1, r2, r3, addr);
                uint32_t b0[2] = {r0, r1}, b1[2] = {r2, r3};
                mma16816(o[2 * dn],     pf[jk], b0);
                mma16816(o[2 * dn + 1], pf[jk], b1);
            }
        }
        __syncthreads();
    }

    // epilogue: fp16 into g_yh[b, q, h*128 + d]
    const int b = bh >> 4, h = bh & 15;
    const float inv0 = 1.f / L0, inv1 = 1.f / L1;
    __half* dst0 = g_yh + (size_t)(b * CL + qg0) * CE + h * CHD;
    __half* dst1 = dst0 + (size_t)8 * CE;
#pragma unroll
    for (int nt = 0; nt < 16; nt++) {
        int d = nt * 8 + (lane & 3) * 2;
        __half2 h0 = __floats2half2_rn(o[nt][0] * inv0, o[nt][1] * inv0);
        __half2 h1 = __floats2half2_rn(o[nt][2] * inv1, o[nt][3] * inv1);
        *(__half2*)(dst0 + d) = h0;
        *(__half2*)(dst1 + d) = h1;
    }
}

// ---------------- host launcher ---------------------------------------------
extern "C" void kernel_launch(void* const* d_in, const int* in_sizes, int n_in,
                              void* d_out, int out_size) {
    const float* x      = (const float*)d_in[0];
    const float* rope   = (const float*)d_in[1];
    const float* w_attn = (const float*)d_in[2];
    const float* w_proj = (const float*)d_in[3];
    float* out = (float*)d_out;

    float *qkv_p;
    __half *xh_p, *wah_p, *wph_p, *yh_p;
    cudaGetSymbolAddress((void**)&qkv_p, g_qkv);
    cudaGetSymbolAddress((void**)&xh_p,  g_xh);
    cudaGetSymbolAddress((void**)&wah_p, g_wah);
    cudaGetSymbolAddress((void**)&wph_p, g_wph);
    cudaGetSymbolAddress((void**)&yh_p,  g_yh);

    cudaFuncSetAttribute(hgemm_mma, cudaFuncAttributeMaxDynamicSharedMemorySize,
                         GEMM_SMEM);
    cudaFuncSetAttribute(flash_mma, cudaFuncAttributeMaxDynamicSharedMemorySize,
                         FLASH_SMEM);

    // 0) fp32 -> fp16 converts
    f32to16<<<(CM * CE / 4) / 256, 256>>>(x, xh_p);
    f32to16<<<(C3E * CE / 4) / 256, 256>>>(w_attn, wah_p);
    f32to16<<<(CE * CE / 4) / 256, 256>>>(w_proj, wph_p);

    // 1) qkv = x @ w_attn^T   [4096, 6144]  (HMMA fp16, 4-stage pipeline)
    hgemm_mma<<<dim3(C3E / BN, CM / BM), 256, GEMM_SMEM>>>(xh_p, wah_p, qkv_p,
                                                           CM, C3E, CE);

    // 2) rope + split into head-major fp16 q/k/v
    rope_split<<<(CB * CL * CH * 64) / 256, 256>>>(rope);

    // 3) causal flash attention (HMMA) -> g_yh (fp16)
    flash_mma<<<dim3(CL / FBQ, CB * CH), 128, FLASH_SMEM>>>();

    // 4) out = y @ w_proj^T   [4096, 2048]  (HMMA fp16)
    hgemm_mma<<<dim3(CE / BN, CM / BM), 256, GEMM_SMEM>>>(yh_p, wph_p, out,
                                                          CM, CE, CE);
}